// round 12
// baseline (speedup 1.0000x reference)
#include <cuda_runtime.h>
#include <cstdint>

// VINeuralODE: B=128, D=32, H=128, 8 Dopri5 steps x 6 field evals.
// dlogpdt = -tr(W3 D2 W2 D1 W1) = -sum_u d1_u (M[u,:]·d2), M precomputed.
// R11: x-integration fully inside the compute group (warps 0-3): each stage is
// h1 -> h2 -> per-warp dxdt chunks (W3 rows 8w..8w+7, 4 lanes/row) + dopri5
// update, with only 3 block-path barriers and NO cross-group round trip.
// Warps 4-7: pure trace (one full M row per thread), joined via bar6(256)
// which is both "h2/d2 ready" and double-buffer backpressure.

#define Dd 32
#define Hh 128
#define NSTEPS 8
#define NST 48

__device__ __align__(16) float d_M[Hh * Hh];

__constant__ float c_C[6]  = {0.0f, 0.2f, 0.3f, 0.8f, 0.88888888888888888f, 1.0f};
__constant__ float c_BW[6] = {35.0f/384.0f, 0.0f, 500.0f/1113.0f, 125.0f/192.0f,
                              -2187.0f/6784.0f, 11.0f/84.0f};

#define BAR_SYNC(id, cnt)   asm volatile("bar.sync %0, %1;"   :: "r"(id), "r"(cnt) : "memory")

__global__ void precompute_M_kernel(const float* __restrict__ W1,
                                    const float* __restrict__ W2,
                                    const float* __restrict__ W3) {
    int jj = blockIdx.x;
    int kk = threadIdx.x;
    float a = 0.f;
#pragma unroll
    for (int i = 0; i < Dd; ++i)
        a += W1[kk * Dd + i] * W3[i * Hh + jj];
    d_M[kk * Hh + jj] = a * W2[jj * Hh + kk];
}

__device__ __forceinline__ float ftanh(float x) {
    float e = __expf(2.0f * x);
    return 1.0f - __fdividef(2.0f, e + 1.0f);
}

__device__ __forceinline__ uint64_t ffma2(uint64_t a, uint64_t b, uint64_t c) {
    uint64_t d;
    asm("fma.rn.f32x2 %0, %1, %2, %3;" : "=l"(d) : "l"(a), "l"(b), "l"(c));
    return d;
}
__device__ __forceinline__ uint64_t pk2(float x, float y) {
    uint64_t r; asm("mov.b64 %0, {%1, %2};" : "=l"(r) : "f"(x), "f"(y)); return r;
}
__device__ __forceinline__ float hsum2(uint64_t v) {
    float a, b; asm("mov.b64 {%0, %1}, %2;" : "=f"(a), "=f"(b) : "l"(v)); return a + b;
}
__device__ __forceinline__ uint32_t sptr(const void* p) {
    return (uint32_t)__cvta_generic_to_shared(p);
}

// 128-length dot, 8 accumulator chains.
__device__ __forceinline__ float dot128(const uint64_t* __restrict__ w, uint32_t saddr) {
    uint64_t a0=0,a1=0,a2=0,a3=0,a4=0,a5=0,a6=0,a7=0;
#pragma unroll
    for (int i = 0; i < 32; i += 4) {
        uint64_t p0,p1,p2,p3,p4,p5,p6,p7;
        asm volatile("ld.shared.v2.u64 {%0, %1}, [%2];" : "=l"(p0), "=l"(p1) : "r"(saddr + 16u*i));
        asm volatile("ld.shared.v2.u64 {%0, %1}, [%2];" : "=l"(p2), "=l"(p3) : "r"(saddr + 16u*i + 16u));
        asm volatile("ld.shared.v2.u64 {%0, %1}, [%2];" : "=l"(p4), "=l"(p5) : "r"(saddr + 16u*i + 32u));
        asm volatile("ld.shared.v2.u64 {%0, %1}, [%2];" : "=l"(p6), "=l"(p7) : "r"(saddr + 16u*i + 48u));
        a0 = ffma2(w[2*i],   p0, a0);
        a1 = ffma2(w[2*i+1], p1, a1);
        a2 = ffma2(w[2*i+2], p2, a2);
        a3 = ffma2(w[2*i+3], p3, a3);
        a4 = ffma2(w[2*i+4], p4, a4);
        a5 = ffma2(w[2*i+5], p5, a5);
        a6 = ffma2(w[2*i+6], p6, a6);
        a7 = ffma2(w[2*i+7], p7, a7);
    }
    return ((hsum2(a0)+hsum2(a1)) + (hsum2(a2)+hsum2(a3)))
         + ((hsum2(a4)+hsum2(a5)) + (hsum2(a6)+hsum2(a7)));
}

// N16 16-byte chunks (N16*4 floats), 4 accumulator chains. N16 must be even.
template <int N16>
__device__ __forceinline__ float dotN(const uint64_t* __restrict__ w, uint32_t saddr) {
    uint64_t a0=0,a1=0,a2=0,a3=0;
#pragma unroll
    for (int i = 0; i < N16; i += 2) {
        uint64_t p0,p1,p2,p3;
        asm volatile("ld.shared.v2.u64 {%0, %1}, [%2];" : "=l"(p0), "=l"(p1) : "r"(saddr + 16u*i));
        asm volatile("ld.shared.v2.u64 {%0, %1}, [%2];" : "=l"(p2), "=l"(p3) : "r"(saddr + 16u*i + 16u));
        a0 = ffma2(w[2*i],   p0, a0);
        a1 = ffma2(w[2*i+1], p1, a1);
        a2 = ffma2(w[2*i+2], p2, a2);
        a3 = ffma2(w[2*i+3], p3, a3);
    }
    return (hsum2(a0)+hsum2(a1)) + (hsum2(a2)+hsum2(a3));
}

__global__ __launch_bounds__(256, 1)
void ode_kernel(const float* __restrict__ x0,
                const float* __restrict__ W1,
                const float* __restrict__ u1,
                const float* __restrict__ b1,
                const float* __restrict__ W2,
                const float* __restrict__ b2,
                const float* __restrict__ W3,
                const float* __restrict__ b3,
                const float* __restrict__ prec,
                float* __restrict__ out, int B) {
    const int s    = blockIdx.x;
    const int tid  = threadIdx.x;
    const int lane = tid & 31;
    const int warp = tid >> 5;
    const float dt = 1.0f / NSTEPS;
    const float HALF_LOG2PI = 0.9189385332046727f;

    __shared__ __align__(16) float sh_xs[Dd];
    __shared__ __align__(16) float sh_h1[Hh];
    __shared__ __align__(16) float sh_d1[2][Hh];
    __shared__ __align__(16) float sh_h2[2][Hh];
    __shared__ __align__(16) float sh_d2[2][Hh];
    __shared__ float sh_tw[NST][4];       // per-stage trace warp-sums (warps 4-7)
    __shared__ float sh_xh[NST + 1][Dd];
    __shared__ float sh_kd[NST][Dd];
    __shared__ float b1s[Hh], u1s[Hh], b2s[Hh], b3s[Dd], precs[Dd];
    __shared__ float sh_pld[8], sh_pkl[8], sh_lp;

    const uint32_t a_xs = sptr(sh_xs);
    const uint32_t a_h1 = sptr(sh_h1);
    const uint32_t a_h2 = sptr(sh_h2[0]);
    const uint32_t a_d2 = sptr(sh_d2[0]);

    if (tid < Hh) { b1s[tid] = b1[tid]; u1s[tid] = u1[tid]; b2s[tid] = b2[tid]; }
    if (tid < Dd) {
        b3s[tid] = b3[tid]; precs[tid] = prec[tid];
        float xv = x0[s * Dd + tid];
        sh_xs[tid] = xv;
        sh_xh[0][tid] = xv;
    }
    __syncthreads();

    if (warp < 4) {
        // ================= COMPUTE (threads 0-127), H-row j = tid ============
        const int j   = tid;
        const int row = 8 * warp + (lane >> 2);   // owned x-dim (4 lanes/row)
        const int chk = lane & 3;                 // 32-col chunk of W3 row
        uint64_t w1p[16];   // W1[j,0:32] packed
        uint64_t w2p[64];   // W2[j,0:128] packed
        uint64_t w3c[16];   // W3[row, chk*32 : +32] packed
        {
            const float4* p = (const float4*)(W1 + j * Dd);
#pragma unroll
            for (int i = 0; i < 8; ++i) {
                float4 v = p[i];
                w1p[2*i] = pk2(v.x, v.y); w1p[2*i+1] = pk2(v.z, v.w);
            }
        }
        {
            const float4* p = (const float4*)(W2 + j * Hh);
#pragma unroll
            for (int i = 0; i < 32; ++i) {
                float4 v = p[i];
                w2p[2*i] = pk2(v.x, v.y); w2p[2*i+1] = pk2(v.z, v.w);
            }
        }
        {
            const float4* p = (const float4*)(W3 + row * Hh + chk * 32);
#pragma unroll
            for (int i = 0; i < 8; ++i) {
                float4 v = p[i];
                w3c[2*i] = pk2(v.x, v.y); w3c[2*i+1] = pk2(v.z, v.w);
            }
        }
        const float b1j = b1s[j], u1j = u1s[j], b2j = b2s[j];
        const float b3r = b3s[row];
        float yv = x0[s * Dd + row];
        float k0 = 0.f, k1 = 0.f, k2 = 0.f, k3 = 0.f, k4 = 0.f;

#pragma unroll 1
        for (int gst = 0; gst < NST; ++gst) {
            const int st  = gst % 6;
            const int stp = gst / 6;
            const int buf = gst & 1;
            float ts = ((float)stp + c_C[st]) * dt;

            BAR_SYNC(1, 128);                     // xs ready (prev tail / init)
            // ---- h1 ----
            float a = dotN<8>(w1p, a_xs) + b1j + ts * u1j;
            float h1 = ftanh(a);
            sh_h1[j] = h1;
            sh_d1[buf][j] = 1.f - h1 * h1;
            BAR_SYNC(1, 128);                     // h1 ready
            // ---- h2 ----
            float b = dot128(w2p, a_h1) + b2j;
            float h2 = ftanh(b);
            sh_h2[buf][j] = h2;
            sh_d2[buf][j] = 1.f - h2 * h2;
            BAR_SYNC(6, 256);                     // h2/d2 ready + trace backpressure
            // ---- dxdt mini: row, chunk chk; 4-lane group reduce ----
            float part = dotN<8>(w3c, a_h2 + 512u * buf + 128u * (uint32_t)chk);
            part += __shfl_xor_sync(0xffffffffu, part, 1);
            part += __shfl_xor_sync(0xffffffffu, part, 2);
            float dxv = part + b3r;
            float acc;
            switch (st) {
                case 0: k0 = dxv; acc = 0.2f * k0; break;
                case 1: k1 = dxv; acc = (3.f/40.f) * k0 + (9.f/40.f) * k1; break;
                case 2: k2 = dxv; acc = (44.f/45.f) * k0 + (-56.f/15.f) * k1 + (32.f/9.f) * k2; break;
                case 3: k3 = dxv; acc = (19372.f/6561.f) * k0 + (-25360.f/2187.f) * k1
                                      + (64448.f/6561.f) * k2 + (-212.f/729.f) * k3; break;
                case 4: k4 = dxv; acc = (9017.f/3168.f) * k0 + (-355.f/33.f) * k1
                                      + (46732.f/5247.f) * k2 + (49.f/176.f) * k3
                                      + (-5103.f/18656.f) * k4; break;
                default:
                    yv = yv + dt * ( (35.f/384.f)     * k0
                                   + (500.f/1113.f)   * k2
                                   + (125.f/192.f)    * k3
                                   + (-2187.f/6784.f) * k4
                                   + (11.f/84.f)      * dxv );
                    acc = 0.f; break;
            }
            float xnew = (st < 5) ? (yv + dt * acc) : yv;
            if (chk == 0) {
                sh_kd[gst][row]     = dxv;
                sh_xs[row]          = xnew;
                sh_xh[gst + 1][row] = xnew;
            }
        }
        if (chk == 0) out[s * Dd + row] = yv;     // final z
    } else {
        // ================= TRACE (warps 4-7, 128 threads): M row u ===========
        const int u  = tid - 128;        // 0..127
        const int tw = warp - 4;         // 0..3
        uint64_t wmp[64];                // M[u, 0:128] packed
        {
            const float4* p = (const float4*)(d_M + u * Hh);
#pragma unroll
            for (int i = 0; i < 32; ++i) {
                float4 va = p[i];
                wmp[2*i] = pk2(va.x, va.y); wmp[2*i+1] = pk2(va.z, va.w);
            }
        }
#pragma unroll 1
        for (int gst = 0; gst < NST; ++gst) {
            const int buf = gst & 1;
            BAR_SYNC(6, 256);                     // h2/d2[buf] ready

            float val = sh_d1[buf][u] * dot128(wmp, a_d2 + 512u * buf);
#pragma unroll
            for (int off = 16; off > 0; off >>= 1)
                val += __shfl_xor_sync(0xffffffffu, val, off);
            if (lane == 0) sh_tw[gst][tw] = val;
        }
    }
    __syncthreads();

    // ================= FINAL EPILOGUE: 48 stage reductions over 8 warps ======
    {
        float acc_ld = 0.f, acc_kl = 0.f;
#pragma unroll 1
        for (int i = 0; i < 6; ++i) {
            int g = warp + 8 * i;
            int st = g % 6;
            int stp = g / 6;
            float ts = ((float)stp + c_C[st]) * dt;
            float dlogp = -((sh_tw[g][0] + sh_tw[g][1]) + (sh_tw[g][2] + sh_tw[g][3]));
            float omt = 1.f - ts;
            float cA = -0.5f * omt * omt;
            float cB = -0.5f * omt * (1.f + ts);
            float xv  = sh_xh[g][lane];
            float dxv = sh_kd[g][lane];
            float qv = (cA * (-0.5f * xv * xv - HALF_LOG2PI) + cB * (-precs[lane] * xv)) * dxv;
#pragma unroll
            for (int off = 16; off > 0; off >>= 1)
                qv += __shfl_xor_sync(0xffffffffu, qv, off);
            float bw = c_BW[st];
            acc_ld += bw * dlogp;
            acc_kl += bw * (qv + omt * dlogp);
        }
        if (lane == 0) { sh_pld[warp] = acc_ld; sh_pkl[warp] = acc_kl; }
        if (warp == 1) {
            float xv = x0[s * Dd + lane];
            float lp = -0.5f * xv * xv - HALF_LOG2PI;
#pragma unroll
            for (int off = 16; off > 0; off >>= 1)
                lp += __shfl_xor_sync(0xffffffffu, lp, off);
            if (lane == 0) sh_lp = lp;
        }
    }
    __syncthreads();
    if (tid == 0) {
        float ld = 0.f, kl = 0.f;
#pragma unroll
        for (int w = 0; w < 8; ++w) { ld += sh_pld[w]; kl += sh_pkl[w]; }
        out[B * Dd + s]     = sh_lp + dt * ld;
        out[B * Dd + B + s] = dt * kl;
    }
}

extern "C" void kernel_launch(void* const* d_in, const int* in_sizes, int n_in,
                              void* d_out, int out_size) {
    const float* x0   = (const float*)d_in[0];
    const float* W1   = (const float*)d_in[1];
    const float* u1   = (const float*)d_in[2];
    const float* b1   = (const float*)d_in[3];
    const float* W2   = (const float*)d_in[4];
    const float* b2   = (const float*)d_in[5];
    const float* W3   = (const float*)d_in[6];
    const float* b3   = (const float*)d_in[7];
    const float* prec = (const float*)d_in[8];
    float* out = (float*)d_out;
    const int B = in_sizes[0] / Dd;

    precompute_M_kernel<<<Hh, Hh>>>(W1, W2, W3);
    ode_kernel<<<B, 256>>>(x0, W1, u1, b1, W2, b2, W3, b3, prec, out, B);
}

// round 15
// speedup vs baseline: 1.1584x; 1.1584x over previous
#include <cuda_runtime.h>
#include <cstdint>

// VINeuralODE: B=128, D=32, H=128, 8 Dopri5 steps x 6 field evals.
// dlogpdt = -tr(W3 D2 W2 D1 W1) = -sum_u d1_u (M[u,:]·d2), M precomputed.
// R13 = R11 topology (3 barrier events/stage; x-integration inside compute
// warps 0-3; warps 4-7 pure M-trace) with data placement fixed:
//   - W1 lives in PADDED SHARED (stride 34 floats) -> compute regs ~200, no spill
//   - h2/d2 stored QUARTER-INTERLEAVED so the per-warp W3 minidot's 4 lane
//     groups read adjacent 16B chunks (1 wavefront, no 4-way conflict).
//     M rows / W3 chunks are register-packed in the matching permutation.

#define Dd 32
#define Hh 128
#define NSTEPS 8
#define NST 48
#define W1S 34   // padded row stride (floats) for W1 in shared

__device__ __align__(16) float d_M[Hh * Hh];

__constant__ float c_C[6]  = {0.0f, 0.2f, 0.3f, 0.8f, 0.88888888888888888f, 1.0f};
__constant__ float c_BW[6] = {35.0f/384.0f, 0.0f, 500.0f/1113.0f, 125.0f/192.0f,
                              -2187.0f/6784.0f, 11.0f/84.0f};

#define BAR_SYNC(id, cnt)   asm volatile("bar.sync %0, %1;"   :: "r"(id), "r"(cnt) : "memory")

__global__ void precompute_M_kernel(const float* __restrict__ W1,
                                    const float* __restrict__ W2,
                                    const float* __restrict__ W3) {
    int jj = blockIdx.x;
    int kk = threadIdx.x;
    float a = 0.f;
#pragma unroll
    for (int i = 0; i < Dd; ++i)
        a += W1[kk * Dd + i] * W3[i * Hh + jj];
    d_M[kk * Hh + jj] = a * W2[jj * Hh + kk];
}

__device__ __forceinline__ float ftanh(float x) {
    float e = __expf(2.0f * x);
    return 1.0f - __fdividef(2.0f, e + 1.0f);
}

__device__ __forceinline__ uint64_t ffma2(uint64_t a, uint64_t b, uint64_t c) {
    uint64_t d;
    asm("fma.rn.f32x2 %0, %1, %2, %3;" : "=l"(d) : "l"(a), "l"(b), "l"(c));
    return d;
}
__device__ __forceinline__ uint64_t pk2(float x, float y) {
    uint64_t r; asm("mov.b64 %0, {%1, %2};" : "=l"(r) : "f"(x), "f"(y)); return r;
}
__device__ __forceinline__ float hsum2(uint64_t v) {
    float a, b; asm("mov.b64 {%0, %1}, %2;" : "=f"(a), "=f"(b) : "l"(v)); return a + b;
}
__device__ __forceinline__ uint32_t sptr(const void* p) {
    return (uint32_t)__cvta_generic_to_shared(p);
}

// 128-length dot, 8 accumulator chains, uniform addresses.
__device__ __forceinline__ float dot128(const uint64_t* __restrict__ w, uint32_t saddr) {
    uint64_t a0=0,a1=0,a2=0,a3=0,a4=0,a5=0,a6=0,a7=0;
#pragma unroll
    for (int i = 0; i < 32; i += 4) {
        uint64_t p0,p1,p2,p3,p4,p5,p6,p7;
        asm volatile("ld.shared.v2.u64 {%0, %1}, [%2];" : "=l"(p0), "=l"(p1) : "r"(saddr + 16u*i));
        asm volatile("ld.shared.v2.u64 {%0, %1}, [%2];" : "=l"(p2), "=l"(p3) : "r"(saddr + 16u*i + 16u));
        asm volatile("ld.shared.v2.u64 {%0, %1}, [%2];" : "=l"(p4), "=l"(p5) : "r"(saddr + 16u*i + 32u));
        asm volatile("ld.shared.v2.u64 {%0, %1}, [%2];" : "=l"(p6), "=l"(p7) : "r"(saddr + 16u*i + 48u));
        a0 = ffma2(w[2*i],   p0, a0);
        a1 = ffma2(w[2*i+1], p1, a1);
        a2 = ffma2(w[2*i+2], p2, a2);
        a3 = ffma2(w[2*i+3], p3, a3);
        a4 = ffma2(w[2*i+4], p4, a4);
        a5 = ffma2(w[2*i+5], p5, a5);
        a6 = ffma2(w[2*i+6], p6, a6);
        a7 = ffma2(w[2*i+7], p7, a7);
    }
    return ((hsum2(a0)+hsum2(a1)) + (hsum2(a2)+hsum2(a3)))
         + ((hsum2(a4)+hsum2(a5)) + (hsum2(a6)+hsum2(a7)));
}

__global__ __launch_bounds__(256, 1)
void ode_kernel(const float* __restrict__ x0,
                const float* __restrict__ W1,
                const float* __restrict__ u1,
                const float* __restrict__ b1,
                const float* __restrict__ W2,
                const float* __restrict__ b2,
                const float* __restrict__ W3,
                const float* __restrict__ b3,
                const float* __restrict__ prec,
                float* __restrict__ out, int B) {
    const int s    = blockIdx.x;
    const int tid  = threadIdx.x;
    const int lane = tid & 31;
    const int warp = tid >> 5;
    const float dt = 1.0f / NSTEPS;
    const float HALF_LOG2PI = 0.9189385332046727f;

    __shared__ __align__(16) float sh_W1s[Hh * W1S];   // padded W1
    __shared__ __align__(16) float sh_xs[Dd];
    __shared__ __align__(16) float sh_h1[Hh];          // linear
    __shared__ __align__(16) float sh_d1[2][Hh];       // linear (scalar reads)
    __shared__ __align__(16) float sh_h2[2][Hh];       // quarter-interleaved
    __shared__ __align__(16) float sh_d2[2][Hh];       // quarter-interleaved
    __shared__ float sh_tw[NST][4];
    __shared__ float sh_xh[NST + 1][Dd];
    __shared__ float sh_kd[NST][Dd];
    __shared__ float b1s[Hh], u1s[Hh], b2s[Hh], b3s[Dd], precs[Dd];
    __shared__ float sh_pld[8], sh_pkl[8], sh_lp;

    const uint32_t a_xs  = sptr(sh_xs);
    const uint32_t a_h1  = sptr(sh_h1);
    const uint32_t a_h2  = sptr(sh_h2[0]);
    const uint32_t a_d2  = sptr(sh_d2[0]);
    const uint32_t a_w1s = sptr(sh_W1s);

    if (tid < Hh) { b1s[tid] = b1[tid]; u1s[tid] = u1[tid]; b2s[tid] = b2[tid]; }
    if (tid < Dd) {
        b3s[tid] = b3[tid]; precs[tid] = prec[tid];
        float xv = x0[s * Dd + tid];
        sh_xs[tid] = xv;
        sh_xh[0][tid] = xv;
    }
    // stage W1 into padded shared
    for (int idx = tid; idx < Hh * Dd; idx += 256)
        sh_W1s[(idx >> 5) * W1S + (idx & 31)] = W1[idx];
    __syncthreads();

    if (warp < 4) {
        // ================= COMPUTE (threads 0-127), H-row j = tid ============
        const int j   = tid;
        const int row = 8 * warp + (lane >> 2);   // owned x-dim (4 lanes/row)
        const int chk = lane & 3;                 // quarter of W3 row
        uint64_t w2p[64];   // W2[j,0:128] packed
        uint64_t w3c[16];   // W3[row, chk*32 : +32] packed (matches interleave)
        {
            const float4* p = (const float4*)(W2 + j * Hh);
#pragma unroll
            for (int i = 0; i < 32; ++i) {
                float4 v = p[i];
                w2p[2*i] = pk2(v.x, v.y); w2p[2*i+1] = pk2(v.z, v.w);
            }
        }
        {
            const float4* p = (const float4*)(W3 + row * Hh + chk * 32);
#pragma unroll
            for (int i = 0; i < 8; ++i) {
                float4 v = p[i];
                w3c[2*i] = pk2(v.x, v.y); w3c[2*i+1] = pk2(v.z, v.w);
            }
        }
        const float b1j = b1s[j], u1j = u1s[j], b2j = b2s[j];
        const float b3r = b3s[row];
        // interleaved write position for own row j (float index)
        const uint32_t ipj = (uint32_t)(((j & 31) >> 2) * 16 + (j >> 5) * 4 + (j & 3));
        const uint32_t aw1 = a_w1s + (uint32_t)j * (W1S * 4);
        float yv = x0[s * Dd + row];
        float k0 = 0.f, k1 = 0.f, k2 = 0.f, k3 = 0.f, k4 = 0.f;

#pragma unroll 1
        for (int gst = 0; gst < NST; ++gst) {
            const int st  = gst % 6;
            const int stp = gst / 6;
            const int buf = gst & 1;
            float ts = ((float)stp + c_C[st]) * dt;

            BAR_SYNC(1, 128);                     // xs ready (prev tail / init)
            // ---- h1: W1 row from padded shared (u64, 2-way max), xs uniform ----
            {
                uint64_t q0=0,q1=0,q2=0,q3=0;
#pragma unroll
                for (int i = 0; i < 16; i += 4) {
                    uint64_t wa,wb,wc,wd, xa,xb,xc,xd;
                    asm volatile("ld.shared.u64 %0, [%1];" : "=l"(wa) : "r"(aw1 + 8u*i));
                    asm volatile("ld.shared.u64 %0, [%1];" : "=l"(wb) : "r"(aw1 + 8u*i + 8u));
                    asm volatile("ld.shared.u64 %0, [%1];" : "=l"(wc) : "r"(aw1 + 8u*i + 16u));
                    asm volatile("ld.shared.u64 %0, [%1];" : "=l"(wd) : "r"(aw1 + 8u*i + 24u));
                    asm volatile("ld.shared.u64 %0, [%1];" : "=l"(xa) : "r"(a_xs + 8u*i));
                    asm volatile("ld.shared.u64 %0, [%1];" : "=l"(xb) : "r"(a_xs + 8u*i + 8u));
                    asm volatile("ld.shared.u64 %0, [%1];" : "=l"(xc) : "r"(a_xs + 8u*i + 16u));
                    asm volatile("ld.shared.u64 %0, [%1];" : "=l"(xd) : "r"(a_xs + 8u*i + 24u));
                    q0 = ffma2(wa, xa, q0);
                    q1 = ffma2(wb, xb, q1);
                    q2 = ffma2(wc, xc, q2);
                    q3 = ffma2(wd, xd, q3);
                }
                float a = (hsum2(q0)+hsum2(q1)) + (hsum2(q2)+hsum2(q3));
                a += b1j + ts * u1j;
                float h1 = ftanh(a);
                sh_h1[j] = h1;
                sh_d1[buf][j] = 1.f - h1 * h1;
            }
            BAR_SYNC(1, 128);                     // h1 ready
            // ---- h2 ----
            float b = dot128(w2p, a_h1) + b2j;
            float h2 = ftanh(b);
            sh_h2[buf][ipj] = h2;
            sh_d2[buf][ipj] = 1.f - h2 * h2;
            BAR_SYNC(6, 256);                     // h2/d2 ready + trace backpressure
            // ---- dxdt minidot: interleaved h2, 1 wavefront per LDS ----
            {
                const uint32_t hb = a_h2 + 512u * (uint32_t)buf + 16u * (uint32_t)chk;
                uint64_t q0=0,q1=0,q2=0,q3=0;
#pragma unroll
                for (int m = 0; m < 8; m += 2) {
                    uint64_t h0,h1_,h2_,h3_;
                    asm volatile("ld.shared.v2.u64 {%0, %1}, [%2];" : "=l"(h0), "=l"(h1_) : "r"(hb + 64u*m));
                    asm volatile("ld.shared.v2.u64 {%0, %1}, [%2];" : "=l"(h2_), "=l"(h3_) : "r"(hb + 64u*m + 64u));
                    q0 = ffma2(w3c[2*m],   h0,  q0);
                    q1 = ffma2(w3c[2*m+1], h1_, q1);
                    q2 = ffma2(w3c[2*m+2], h2_, q2);
                    q3 = ffma2(w3c[2*m+3], h3_, q3);
                }
                float part = (hsum2(q0)+hsum2(q1)) + (hsum2(q2)+hsum2(q3));
                part += __shfl_xor_sync(0xffffffffu, part, 1);
                part += __shfl_xor_sync(0xffffffffu, part, 2);
                float dxv = part + b3r;
                float acc;
                switch (st) {
                    case 0: k0 = dxv; acc = 0.2f * k0; break;
                    case 1: k1 = dxv; acc = (3.f/40.f) * k0 + (9.f/40.f) * k1; break;
                    case 2: k2 = dxv; acc = (44.f/45.f) * k0 + (-56.f/15.f) * k1 + (32.f/9.f) * k2; break;
                    case 3: k3 = dxv; acc = (19372.f/6561.f) * k0 + (-25360.f/2187.f) * k1
                                          + (64448.f/6561.f) * k2 + (-212.f/729.f) * k3; break;
                    case 4: k4 = dxv; acc = (9017.f/3168.f) * k0 + (-355.f/33.f) * k1
                                          + (46732.f/5247.f) * k2 + (49.f/176.f) * k3
                                          + (-5103.f/18656.f) * k4; break;
                    default:
                        yv = yv + dt * ( (35.f/384.f)     * k0
                                       + (500.f/1113.f)   * k2
                                       + (125.f/192.f)    * k3
                                       + (-2187.f/6784.f) * k4
                                       + (11.f/84.f)      * dxv );
                        acc = 0.f; break;
                }
                float xnew = (st < 5) ? (yv + dt * acc) : yv;
                if (chk == 0) {
                    sh_kd[gst][row]     = dxv;
                    sh_xs[row]          = xnew;
                    sh_xh[gst + 1][row] = xnew;
                }
            }
        }
        if (chk == 0) out[s * Dd + row] = yv;     // final z
    } else {
        // ================= TRACE (warps 4-7): M row u, permuted packing ======
        const int u  = tid - 128;        // 0..127
        const int tw = warp - 4;         // 0..3
        uint64_t wmp[64];                // M[u,:] packed to match interleave
        {
            const float* mrow = d_M + u * Hh;
#pragma unroll
            for (int t = 0; t < 32; ++t) {
                // 16B chunk t of interleaved layout = original k = (t&3)*32 + (t>>2)*4 + e
                float4 va = *(const float4*)(mrow + (t & 3) * 32 + (t >> 2) * 4);
                wmp[2*t] = pk2(va.x, va.y); wmp[2*t+1] = pk2(va.z, va.w);
            }
        }
#pragma unroll 1
        for (int gst = 0; gst < NST; ++gst) {
            const int buf = gst & 1;
            BAR_SYNC(6, 256);                     // h2/d2[buf] ready

            float val = sh_d1[buf][u] * dot128(wmp, a_d2 + 512u * buf);
#pragma unroll
            for (int off = 16; off > 0; off >>= 1)
                val += __shfl_xor_sync(0xffffffffu, val, off);
            if (lane == 0) sh_tw[gst][tw] = val;
        }
    }
    __syncthreads();

    // ================= FINAL EPILOGUE: 48 stage reductions over 8 warps ======
    {
        float acc_ld = 0.f, acc_kl = 0.f;
#pragma unroll 1
        for (int i = 0; i < 6; ++i) {
            int g = warp + 8 * i;
            int st = g % 6;
            int stp = g / 6;
            float ts = ((float)stp + c_C[st]) * dt;
            float dlogp = -((sh_tw[g][0] + sh_tw[g][1]) + (sh_tw[g][2] + sh_tw[g][3]));
            float omt = 1.f - ts;
            float cA = -0.5f * omt * omt;
            float cB = -0.5f * omt * (1.f + ts);
            float xv  = sh_xh[g][lane];
            float dxv = sh_kd[g][lane];
            float qv = (cA * (-0.5f * xv * xv - HALF_LOG2PI) + cB * (-precs[lane] * xv)) * dxv;
#pragma unroll
            for (int off = 16; off > 0; off >>= 1)
                qv += __shfl_xor_sync(0xffffffffu, qv, off);
            float bw = c_BW[st];
            acc_ld += bw * dlogp;
            acc_kl += bw * (qv + omt * dlogp);
        }
        if (lane == 0) { sh_pld[warp] = acc_ld; sh_pkl[warp] = acc_kl; }
        if (warp == 1) {
            float xv = x0[s * Dd + lane];
            float lp = -0.5f * xv * xv - HALF_LOG2PI;
#pragma unroll
            for (int off = 16; off > 0; off >>= 1)
                lp += __shfl_xor_sync(0xffffffffu, lp, off);
            if (lane == 0) sh_lp = lp;
        }
    }
    __syncthreads();
    if (tid == 0) {
        float ld = 0.f, kl = 0.f;
#pragma unroll
        for (int w = 0; w < 8; ++w) { ld += sh_pld[w]; kl += sh_pkl[w]; }
        out[B * Dd + s]     = sh_lp + dt * ld;
        out[B * Dd + B + s] = dt * kl;
    }
}

extern "C" void kernel_launch(void* const* d_in, const int* in_sizes, int n_in,
                              void* d_out, int out_size) {
    const float* x0   = (const float*)d_in[0];
    const float* W1   = (const float*)d_in[1];
    const float* u1   = (const float*)d_in[2];
    const float* b1   = (const float*)d_in[3];
    const float* W2   = (const float*)d_in[4];
    const float* b2   = (const float*)d_in[5];
    const float* W3   = (const float*)d_in[6];
    const float* b3   = (const float*)d_in[7];
    const float* prec = (const float*)d_in[8];
    float* out = (float*)d_out;
    const int B = in_sizes[0] / Dd;

    precompute_M_kernel<<<Hh, Hh>>>(W1, W2, W3);
    ode_kernel<<<B, 256>>>(x0, W1, u1, b1, W2, b2, W3, b3, prec, out, B);
}

// round 17
// speedup vs baseline: 1.3775x; 1.1891x over previous
#include <cuda_runtime.h>
#include <cstdint>

// VINeuralODE: B=128, D=32, H=128, 8 Dopri5 steps x 6 field evals.
// dlogpdt = -tr(W3 D2 W2 D1 W1) = -sum_u d1_u (M[u,:]·d2), M precomputed.
// R17 = R8 (best measured: 43.1us) with the stage loop unrolled 8 x (6 stages),
// making st compile-time: dopri switch -> straight-line, constants folded,
// no div/rem, no per-stage branch machinery. Protocol identical to R8.
// (R16 compile fix: constexpr device FUNCTION for the node constants.)

#define Dd 32
#define Hh 128
#define NSTEPS 8
#define NST 48

__device__ __align__(16) float d_M[Hh * Hh];

// compile-time dopri5 node constants (constexpr function: legal in device code)
__host__ __device__ constexpr float ccf(int st) {
    return (st == 0) ? 0.0f
         : (st == 1) ? 0.2f
         : (st == 2) ? 0.3f
         : (st == 3) ? 0.8f
         : (st == 4) ? 0.88888888888888888f
         : 1.0f;
}

__constant__ float c_C[6]  = {0.0f, 0.2f, 0.3f, 0.8f, 0.88888888888888888f, 1.0f};
__constant__ float c_BW[6] = {35.0f/384.0f, 0.0f, 500.0f/1113.0f, 125.0f/192.0f,
                              -2187.0f/6784.0f, 11.0f/84.0f};

#define BAR_SYNC(id, cnt)   asm volatile("bar.sync %0, %1;"   :: "r"(id), "r"(cnt) : "memory")
#define BAR_ARRIVE(id, cnt) asm volatile("bar.arrive %0, %1;" :: "r"(id), "r"(cnt) : "memory")

__global__ void precompute_M_kernel(const float* __restrict__ W1,
                                    const float* __restrict__ W2,
                                    const float* __restrict__ W3) {
    int jj = blockIdx.x;
    int kk = threadIdx.x;
    float a = 0.f;
#pragma unroll
    for (int i = 0; i < Dd; ++i)
        a += W1[kk * Dd + i] * W3[i * Hh + jj];
    d_M[kk * Hh + jj] = a * W2[jj * Hh + kk];
}

__device__ __forceinline__ float ftanh(float x) {
    float e = __expf(2.0f * x);
    return 1.0f - __fdividef(2.0f, e + 1.0f);
}

__device__ __forceinline__ uint64_t ffma2(uint64_t a, uint64_t b, uint64_t c) {
    uint64_t d;
    asm("fma.rn.f32x2 %0, %1, %2, %3;" : "=l"(d) : "l"(a), "l"(b), "l"(c));
    return d;
}
__device__ __forceinline__ uint64_t pk2(float x, float y) {
    uint64_t r; asm("mov.b64 %0, {%1, %2};" : "=l"(r) : "f"(x), "f"(y)); return r;
}
__device__ __forceinline__ float hsum2(uint64_t v) {
    float a, b; asm("mov.b64 {%0, %1}, %2;" : "=f"(a), "=f"(b) : "l"(v)); return a + b;
}
__device__ __forceinline__ uint32_t sptr(const void* p) {
    return (uint32_t)__cvta_generic_to_shared(p);
}

// 128-length dot: weights packed (64 x u64), activations in shared at saddr.
__device__ __forceinline__ float dot128(const uint64_t* __restrict__ w, uint32_t saddr) {
    uint64_t a0 = 0, a1 = 0, a2 = 0, a3 = 0;
#pragma unroll
    for (int i = 0; i < 32; i += 2) {
        uint64_t p0, p1, p2, p3;
        asm volatile("ld.shared.v2.u64 {%0, %1}, [%2];" : "=l"(p0), "=l"(p1) : "r"(saddr + 16u * i));
        asm volatile("ld.shared.v2.u64 {%0, %1}, [%2];" : "=l"(p2), "=l"(p3) : "r"(saddr + 16u * i + 16u));
        a0 = ffma2(w[2*i],   p0, a0);
        a1 = ffma2(w[2*i+1], p1, a1);
        a2 = ffma2(w[2*i+2], p2, a2);
        a3 = ffma2(w[2*i+3], p3, a3);
    }
    return (hsum2(a0) + hsum2(a1)) + (hsum2(a2) + hsum2(a3));
}

// 32-length dot: weights packed (16 x u64), activations in shared at saddr.
__device__ __forceinline__ float dot32(const uint64_t* __restrict__ w, uint32_t saddr) {
    uint64_t a0 = 0, a1 = 0;
#pragma unroll
    for (int i = 0; i < 8; ++i) {
        uint64_t p0, p1;
        asm volatile("ld.shared.v2.u64 {%0, %1}, [%2];" : "=l"(p0), "=l"(p1) : "r"(saddr + 16u * i));
        a0 = ffma2(w[2*i],   p0, a0);
        a1 = ffma2(w[2*i+1], p1, a1);
    }
    return hsum2(a0) + hsum2(a1);
}

__global__ __launch_bounds__(256, 1)
void ode_kernel(const float* __restrict__ x0,
                const float* __restrict__ W1,
                const float* __restrict__ u1,
                const float* __restrict__ b1,
                const float* __restrict__ W2,
                const float* __restrict__ b2,
                const float* __restrict__ W3,
                const float* __restrict__ b3,
                const float* __restrict__ prec,
                float* __restrict__ out, int B) {
    const int s    = blockIdx.x;
    const int tid  = threadIdx.x;
    const int lane = tid & 31;
    const int warp = tid >> 5;
    const float dt = 1.0f / NSTEPS;
    const float HALF_LOG2PI = 0.9189385332046727f;

    __shared__ __align__(16) float sh_xs[Dd];
    __shared__ __align__(16) float sh_h1[Hh];
    __shared__ __align__(16) float sh_d1[2][Hh];
    __shared__ __align__(16) float sh_h2[Hh];
    __shared__ __align__(16) float sh_d2[Hh];
    __shared__ float sh_dxp[Hh];          // W3 quarter partials (warps 5-7 -> idx 32..127)
    __shared__ float sh_tw[NST][4];       // per-stage trace warp-sums
    __shared__ float sh_xh[NST + 1][Dd];  // x snapshot per stage (written by warp4)
    __shared__ float sh_kd[NST][Dd];      // dxdt per stage
    __shared__ float b1s[Hh], u1s[Hh], b2s[Hh], b3s[Dd], precs[Dd];
    __shared__ float sh_pld[8], sh_pkl[8], sh_lp;

    const uint32_t a_xs = sptr(sh_xs);
    const uint32_t a_h1 = sptr(sh_h1);
    const uint32_t a_h2 = sptr(sh_h2);
    const uint32_t a_d2 = sptr(sh_d2);

    if (tid < Hh) { b1s[tid] = b1[tid]; u1s[tid] = u1[tid]; b2s[tid] = b2[tid]; }
    if (tid < Dd) {
        b3s[tid] = b3[tid]; precs[tid] = prec[tid];
        float xv = x0[s * Dd + tid];
        sh_xs[tid] = xv;
        sh_xh[0][tid] = xv;
    }
    __syncthreads();

    if (warp < 4) {
        // ================= COMPUTE (threads 0-127), H-row j = tid ============
        const int j = tid;
        uint64_t w1p[16];   // W1[j,0:32] packed
        uint64_t w2p[64];   // W2[j,0:128] packed
        {
            const float4* p = (const float4*)(W1 + j * Dd);
#pragma unroll
            for (int i = 0; i < 8; ++i) {
                float4 v = p[i];
                w1p[2*i] = pk2(v.x, v.y); w1p[2*i+1] = pk2(v.z, v.w);
            }
        }
        {
            const float4* p = (const float4*)(W2 + j * Hh);
#pragma unroll
            for (int i = 0; i < 32; ++i) {
                float4 v = p[i];
                w2p[2*i] = pk2(v.x, v.y); w2p[2*i+1] = pk2(v.z, v.w);
            }
        }
        const float b1j = b1s[j], u1j = u1s[j], b2j = b2s[j];

#pragma unroll 1
        for (int step = 0; step < NSTEPS; ++step) {
            const float fstep = (float)step;
#pragma unroll
            for (int st = 0; st < 6; ++st) {
                const int buf = st & 1;             // (6*step + st) & 1 == st & 1
                float ts = (fstep + ccf(st)) * dt;  // folds to immediate

                BAR_SYNC(5, 160);                 // xs ready (from warp4 / prime)
                // ---- h1 ----
                float a = dot32(w1p, a_xs) + b1j + ts * u1j;
                float h1 = ftanh(a);
                sh_h1[j] = h1;
                sh_d1[buf][j] = 1.f - h1 * h1;
                BAR_SYNC(1, 128);                 // all h1 written
                // ---- h2 ----
                float b = dot128(w2p, a_h1) + b2j;
                float h2 = ftanh(b);
                BAR_SYNC(3, 256);                 // trace consumed old h2/d2
                sh_h2[j] = h2;
                sh_d2[j] = 1.f - h2 * h2;
                BAR_ARRIVE(2, 256);               // h2/d2 ready
            }
        }
    } else {
        // ================= TRACE (threads 128-255) ===========================
        const int u  = tid - 128;        // 0..127
        const int tw = warp - 4;         // 0..3 (W3 column quarter)
        const int rw = u & 31;           // W3 output row
        uint64_t wmp[64];   // M[u,0:128] packed
        uint64_t w3p[16];   // W3[rw, tw*32 : +32] packed
        {
            const float4* p = (const float4*)(d_M + u * Hh);
#pragma unroll
            for (int i = 0; i < 32; ++i) {
                float4 v = p[i];
                wmp[2*i] = pk2(v.x, v.y); wmp[2*i+1] = pk2(v.z, v.w);
            }
        }
        {
            const float4* p = (const float4*)(W3 + rw * Hh + tw * 32);
#pragma unroll
            for (int i = 0; i < 8; ++i) {
                float4 v = p[i];
                w3p[2*i] = pk2(v.x, v.y); w3p[2*i+1] = pk2(v.z, v.w);
            }
        }
        float yv = 0.f, k0 = 0.f, k1 = 0.f, k2 = 0.f, k3 = 0.f, k4 = 0.f;
        if (tw == 0) yv = x0[s * Dd + lane];

        // prime barriers
        BAR_ARRIVE(3, 256);                       // "d2 consumed"
        if (tw == 0) BAR_ARRIVE(5, 160);          // "xs ready" (init xs = x0)

#pragma unroll 1
        for (int step = 0; step < NSTEPS; ++step) {
#pragma unroll
            for (int st = 0; st < 6; ++st) {
                const int gst = step * 6 + st;
                const int buf = st & 1;
                BAR_SYNC(2, 256);                 // h2/d2 ready

                // ---- W3 quarter dot: row rw, cols tw*32..+31 ----
                float qd = dot32(w3p, a_h2 + 4u * (tw * 32));

                if (tw == 0) {
                    // warp 4: gather partials, dxdt, dopri5 update (st compile-time)
                    BAR_SYNC(4, 128);             // warps 5-7 partials ready
                    float dxv = qd + ((sh_dxp[32 + lane] + sh_dxp[64 + lane])
                                    + sh_dxp[96 + lane]) + b3s[lane];
                    sh_kd[gst][lane] = dxv;
                    float acc = 0.f;
                    if (st == 0)      { k0 = dxv; acc = 0.2f * k0; }
                    else if (st == 1) { k1 = dxv; acc = (3.f/40.f) * k0 + (9.f/40.f) * k1; }
                    else if (st == 2) { k2 = dxv; acc = (44.f/45.f) * k0 + (-56.f/15.f) * k1
                                                      + (32.f/9.f) * k2; }
                    else if (st == 3) { k3 = dxv; acc = (19372.f/6561.f) * k0 + (-25360.f/2187.f) * k1
                                                      + (64448.f/6561.f) * k2 + (-212.f/729.f) * k3; }
                    else if (st == 4) { k4 = dxv; acc = (9017.f/3168.f) * k0 + (-355.f/33.f) * k1
                                                      + (46732.f/5247.f) * k2 + (49.f/176.f) * k3
                                                      + (-5103.f/18656.f) * k4; }
                    else {
                        yv = yv + dt * ( (35.f/384.f)     * k0
                                       + (500.f/1113.f)   * k2
                                       + (125.f/192.f)    * k3
                                       + (-2187.f/6784.f) * k4
                                       + (11.f/84.f)      * dxv );
                    }
                    float xnew = (st < 5) ? (yv + dt * acc) : yv;
                    sh_xs[lane] = xnew;
                    sh_xh[gst + 1][lane] = xnew;
                    BAR_ARRIVE(5, 160);           // xs ready
                } else {
                    sh_dxp[u] = qd;
                    BAR_ARRIVE(4, 128);           // partial ready for warp 4
                }

                // ---- M-row trace dot (off critical path) ----
                float val = sh_d1[buf][u] * dot128(wmp, a_d2);
                BAR_ARRIVE(3, 256);               // d2 consumed

#pragma unroll
                for (int off = 16; off > 0; off >>= 1)
                    val += __shfl_xor_sync(0xffffffffu, val, off);
                if (lane == 0) sh_tw[gst][tw] = val;
            }
        }
        if (tw == 0) out[s * Dd + lane] = yv;     // final z
    }
    __syncthreads();

    // ================= FINAL EPILOGUE: 48 stage reductions over 8 warps ======
    {
        float acc_ld = 0.f, acc_kl = 0.f;
#pragma unroll 1
        for (int i = 0; i < 6; ++i) {
            int g = warp + 8 * i;
            int st = g % 6;
            int stp = g / 6;
            float ts = ((float)stp + c_C[st]) * dt;
            float dlogp = -((sh_tw[g][0] + sh_tw[g][1]) + (sh_tw[g][2] + sh_tw[g][3]));
            float omt = 1.f - ts;
            float cA = -0.5f * omt * omt;
            float cB = -0.5f * omt * (1.f + ts);
            float xv  = sh_xh[g][lane];
            float dxv = sh_kd[g][lane];
            float qv = (cA * (-0.5f * xv * xv - HALF_LOG2PI) + cB * (-precs[lane] * xv)) * dxv;
#pragma unroll
            for (int off = 16; off > 0; off >>= 1)
                qv += __shfl_xor_sync(0xffffffffu, qv, off);
            float bw = c_BW[st];
            acc_ld += bw * dlogp;
            acc_kl += bw * (qv + omt * dlogp);
        }
        if (lane == 0) { sh_pld[warp] = acc_ld; sh_pkl[warp] = acc_kl; }
        if (warp == 1) {
            float xv = x0[s * Dd + lane];
            float lp = -0.5f * xv * xv - HALF_LOG2PI;
#pragma unroll
            for (int off = 16; off > 0; off >>= 1)
                lp += __shfl_xor_sync(0xffffffffu, lp, off);
            if (lane == 0) sh_lp = lp;
        }
    }
    __syncthreads();
    if (tid == 0) {
        float ld = 0.f, kl = 0.f;
#pragma unroll
        for (int w = 0; w < 8; ++w) { ld += sh_pld[w]; kl += sh_pkl[w]; }
        out[B * Dd + s]     = sh_lp + dt * ld;
        out[B * Dd + B + s] = dt * kl;
    }
}

extern "C" void kernel_launch(void* const* d_in, const int* in_sizes, int n_in,
                              void* d_out, int out_size) {
    const float* x0   = (const float*)d_in[0];
    const float* W1   = (const float*)d_in[1];
    const float* u1   = (const float*)d_in[2];
    const float* b1   = (const float*)d_in[3];
    const float* W2   = (const float*)d_in[4];
    const float* b2   = (const float*)d_in[5];
    const float* W3   = (const float*)d_in[6];
    const float* b3   = (const float*)d_in[7];
    const float* prec = (const float*)d_in[8];
    float* out = (float*)d_out;
    const int B = in_sizes[0] / Dd;

    precompute_M_kernel<<<Hh, Hh>>>(W1, W2, W3);
    ode_kernel<<<B, 256>>>(x0, W1, u1, b1, W2, b2, W3, b3, prec, out, B);
}